// round 4
// baseline (speedup 1.0000x reference)
#include <cuda_runtime.h>
#include <cuda_bf16.h>
#include <cstdint>

#define N_ATOMS 40000
#define N_PAIRS 640000
#define DD 128
#define RR 20

// Scratch (allocation-free rule: static device globals)
__device__ float g_h[N_ATOMS * DD];    // 20.48 MB
__device__ float g_agg[N_ATOMS * DD];  // 20.48 MB

// Packed fp32x2 FMA (kept for the GEMMs: measured 41.1us vs 45.1us scalar)
#define FFMA2(acc, a, b) \
    asm("fma.rn.f32x2 %0, %1, %2, %0;" : "+l"(acc) : "l"(a), "l"(b))

__device__ __forceinline__ unsigned long long pack2(float x, float y) {
    unsigned long long d;
    asm("mov.b64 %0, {%1,%2};" : "=l"(d) : "f"(x), "f"(y));
    return d;
}
__device__ __forceinline__ void unpack2(unsigned long long d, float& x, float& y) {
    asm("mov.b64 {%0,%1}, %2;" : "=f"(x), "=f"(y) : "l"(d));
}

__device__ __forceinline__ uint32_t to_tf32(float f) {
    uint32_t r;
    asm("cvt.rna.tf32.f32 %0, %1;" : "=r"(r) : "f"(f));
    return r;
}

__device__ __forceinline__ void red_add_v2(float* addr, float a, float b) {
    asm volatile("red.global.add.v2.f32 [%0], {%1, %2};"
                 :: "l"(addr), "f"(a), "f"(b) : "memory");
}

// m16n8k8 tf32 MMA, row.col, fp32 accumulate-in-place
__device__ __forceinline__ void mma8(float& d0, float& d1, float& d2, float& d3,
                                     uint32_t a0, uint32_t a1, uint32_t a2, uint32_t a3,
                                     uint32_t b0, uint32_t b1) {
    asm("mma.sync.aligned.m16n8k8.row.col.f32.tf32.tf32.f32 "
        "{%0,%1,%2,%3}, {%4,%5,%6,%7}, {%8,%9}, {%0,%1,%2,%3};"
        : "+f"(d0), "+f"(d1), "+f"(d2), "+f"(d3)
        : "r"(a0), "r"(a1), "r"(a2), "r"(a3), "r"(b0), "r"(b1));
}

__device__ __forceinline__ float sspf(float x) {
    float sp = (x > 15.f) ? x : __logf(1.f + __expf(x));
    return sp - 0.69314718055994531f;
}

__global__ void zero_kernel(float4* __restrict__ p, int n4) {
    int i = blockIdx.x * blockDim.x + threadIdx.x;
    if (i < n4) p[i] = make_float4(0.f, 0.f, 0.f, 0.f);
}

// -----------------------------------------------------------------------------
// Tiled SGEMM (unchanged from measured-best round-3 version, 41.1us)
// -----------------------------------------------------------------------------
template <bool SSP>
__global__ __launch_bounds__(256) void gemm_atoms(
    const float* __restrict__ A, const float* __restrict__ W,
    const float* __restrict__ bias, float* __restrict__ out, int M)
{
    __shared__ float As[16][68];
    __shared__ float Bs[16][132];

    const int tid  = threadIdx.x;
    const int tcol = tid & 31;
    const int trow = tid >> 5;
    const int a0   = blockIdx.x * 64;

    unsigned long long accp[4][4];
#pragma unroll
    for (int p = 0; p < 4; p++)
#pragma unroll
        for (int j = 0; j < 4; j++) accp[p][j] = 0ull;

    for (int kt = 0; kt < 128; kt += 16) {
        {
            int r = tid >> 2, kg = (tid & 3) << 2;
            float4 v = *(const float4*)&A[(size_t)(a0 + r) * 128 + kt + kg];
            As[kg + 0][r] = v.x; As[kg + 1][r] = v.y;
            As[kg + 2][r] = v.z; As[kg + 3][r] = v.w;
        }
#pragma unroll
        for (int q = 0; q < 2; q++) {
            int idx = tid + q * 256;
            int c = idx >> 2, kg = (idx & 3) << 2;
            float4 v = *(const float4*)&W[(size_t)c * 128 + kt + kg];
            Bs[kg + 0][c] = v.x; Bs[kg + 1][c] = v.y;
            Bs[kg + 2][c] = v.z; Bs[kg + 3][c] = v.w;
        }
        __syncthreads();
#pragma unroll
        for (int k = 0; k < 16; k++) {
            float4 b = *(const float4*)&Bs[k][tcol * 4];
            unsigned long long bb[4];
            bb[0] = pack2(b.x, b.x); bb[1] = pack2(b.y, b.y);
            bb[2] = pack2(b.z, b.z); bb[3] = pack2(b.w, b.w);
            const unsigned long long* ap =
                (const unsigned long long*)&As[k][trow * 8];
            unsigned long long a[4];
            a[0] = ap[0]; a[1] = ap[1]; a[2] = ap[2]; a[3] = ap[3];
#pragma unroll
            for (int p = 0; p < 4; p++)
#pragma unroll
                for (int j = 0; j < 4; j++) FFMA2(accp[p][j], a[p], bb[j]);
        }
        __syncthreads();
    }

    float4 bia = *(const float4*)&bias[tcol * 4];
    float bb[4] = {bia.x, bia.y, bia.z, bia.w};
#pragma unroll
    for (int p = 0; p < 4; p++) {
        float lo[4], hi[4];
#pragma unroll
        for (int j = 0; j < 4; j++) {
            unpack2(accp[p][j], lo[j], hi[j]);
            lo[j] += bb[j]; hi[j] += bb[j];
            if (SSP) { lo[j] = sspf(lo[j]); hi[j] = sspf(hi[j]); }
        }
        size_t r0 = (size_t)(a0 + trow * 8 + 2 * p) * 128 + tcol * 4;
        *(float4*)&out[r0]       = make_float4(lo[0], lo[1], lo[2], lo[3]);
        *(float4*)&out[r0 + 128] = make_float4(hi[0], hi[1], hi[2], hi[3]);
    }
}

// -----------------------------------------------------------------------------
// Pair kernel on tensor pipe (3xTF32 mma.sync):
//   S[p,c] = f_ij[p,:] @ W_f[c,:]        (K=20, padded to 24, 3 k8-steps)
//   Wij = ssp(S + b_f) * rcut;  agg[idx_i] += h[idx_j] * Wij
// CTA: 256 thr, tile 128 pairs x 128 ch. Warp = 64 pairs x 32 ch
// (warps: 2 pair-halves x 4 channel-groups). W_f fragments persistent in regs.
// -----------------------------------------------------------------------------
#define TILE_P 128
#define FSTRIDE 28   // smem row stride (floats): r*28 mod 32 hits distinct banks

__global__ __launch_bounds__(256) void pair_mma_kernel(
    const float* __restrict__ f_ij, const int* __restrict__ idx_i,
    const int* __restrict__ idx_j, const float* __restrict__ rcut,
    const float* __restrict__ W_f, const float* __restrict__ b_f,
    const float* __restrict__ h, float* __restrict__ agg)
{
    __shared__ float sF[TILE_P][FSTRIDE];  // raw fp32 f values, cols 20-23 zeroed
    __shared__ int   sI[TILE_P];
    __shared__ int   sJ[TILE_P];
    __shared__ float sR[TILE_P];

    const int tid   = threadIdx.x;
    const int lane  = tid & 31;
    const int warp  = tid >> 5;
    const int qr    = lane >> 2;        // 0..7
    const int qc    = lane & 3;         // 0..3
    const int cbase = (warp & 3) * 32;  // channel group base
    const int pbw   = (warp >> 2) * 64; // pair half base within tile

    // ---- Persistent B fragments: W_f[ch][k], split hi/lo for 3xTF32 ----
    // b0 = B[k=qc][n=qr], b1 = B[k=qc+4][n=qr]  with n -> channel, per ntile/kstep
    uint32_t bh[4][3][2], bl[4][3][2];
#pragma unroll
    for (int nt = 0; nt < 4; nt++) {
        const int ch = cbase + nt * 8 + qr;
#pragma unroll
        for (int ks = 0; ks < 3; ks++) {
#pragma unroll
            for (int hf = 0; hf < 2; hf++) {
                const int k = ks * 8 + qc + hf * 4;
                float w = (k < RR) ? __ldg(&W_f[ch * RR + k]) : 0.f;
                uint32_t whi = to_tf32(w);
                bh[nt][ks][hf] = whi;
                bl[nt][ks][hf] = to_tf32(w - __uint_as_float(whi));
            }
        }
    }
    float bias[4][2];
#pragma unroll
    for (int nt = 0; nt < 4; nt++) {
        const int ch0 = cbase + nt * 8 + 2 * qc;
        bias[nt][0] = __ldg(&b_f[ch0]);
        bias[nt][1] = __ldg(&b_f[ch0 + 1]);
    }

    const int ntiles = N_PAIRS / TILE_P;
    for (int tile = blockIdx.x; tile < ntiles; tile += gridDim.x) {
        const int base = tile * TILE_P;
        __syncthreads();   // protect smem reuse
        // Stage f (coalesced), raw fp32
#pragma unroll
        for (int it = 0; it < 10; it++) {
            int idx = tid + it * 256;           // 0..2559
            int p = idx / RR, c = idx - p * RR;
            sF[p][c] = f_ij[(size_t)base * RR + idx];
        }
        // Zero K-pad cols 20..23
        {
            int p = tid >> 1, c = 20 + 2 * (tid & 1);
            sF[p][c] = 0.f; sF[p][c + 1] = 0.f;
        }
        if (tid < TILE_P) {
            sI[tid] = idx_i[base + tid];
            sJ[tid] = idx_j[base + tid];
            sR[tid] = rcut[base + tid];
        }
        __syncthreads();

        // ---- MMA: d[mt][nt][4], 64 accumulators ----
        float d[4][4][4];
#pragma unroll
        for (int mt = 0; mt < 4; mt++)
#pragma unroll
            for (int nt = 0; nt < 4; nt++)
#pragma unroll
                for (int e = 0; e < 4; e++) d[mt][nt][e] = 0.f;

#pragma unroll
        for (int ks = 0; ks < 3; ks++) {
#pragma unroll
            for (int mt = 0; mt < 4; mt++) {
                const int r0 = pbw + mt * 16 + qr;
                const int c  = ks * 8 + qc;
                float f0 = sF[r0][c],     f1 = sF[r0 + 8][c];
                float f2 = sF[r0][c + 4], f3 = sF[r0 + 8][c + 4];
                uint32_t ah0 = to_tf32(f0), ah1 = to_tf32(f1);
                uint32_t ah2 = to_tf32(f2), ah3 = to_tf32(f3);
                uint32_t al0 = to_tf32(f0 - __uint_as_float(ah0));
                uint32_t al1 = to_tf32(f1 - __uint_as_float(ah1));
                uint32_t al2 = to_tf32(f2 - __uint_as_float(ah2));
                uint32_t al3 = to_tf32(f3 - __uint_as_float(ah3));
#pragma unroll
                for (int nt = 0; nt < 4; nt++) {
                    mma8(d[mt][nt][0], d[mt][nt][1], d[mt][nt][2], d[mt][nt][3],
                         ah0, ah1, ah2, ah3, bl[nt][ks][0], bl[nt][ks][1]);
                    mma8(d[mt][nt][0], d[mt][nt][1], d[mt][nt][2], d[mt][nt][3],
                         al0, al1, al2, al3, bh[nt][ks][0], bh[nt][ks][1]);
                    mma8(d[mt][nt][0], d[mt][nt][1], d[mt][nt][2], d[mt][nt][3],
                         ah0, ah1, ah2, ah3, bh[nt][ks][0], bh[nt][ks][1]);
                }
            }
        }

        // ---- Epilogue: ssp, cutoff, gather h, modulate, scatter-add ----
#pragma unroll
        for (int mt = 0; mt < 4; mt++) {
            const int p0 = pbw + mt * 16 + qr;
            const int p1 = p0 + 8;
            const float rc0 = sR[p0], rc1 = sR[p1];
            const float* hrow0 = h + (size_t)sJ[p0] * DD;
            const float* hrow1 = h + (size_t)sJ[p1] * DD;
            float* arow0 = agg + (size_t)sI[p0] * DD;
            float* arow1 = agg + (size_t)sI[p1] * DD;
#pragma unroll
            for (int nt = 0; nt < 4; nt++) {
                const int ch0 = cbase + nt * 8 + 2 * qc;
                float w00 = sspf(d[mt][nt][0] + bias[nt][0]) * rc0;
                float w01 = sspf(d[mt][nt][1] + bias[nt][1]) * rc0;
                float w10 = sspf(d[mt][nt][2] + bias[nt][0]) * rc1;
                float w11 = sspf(d[mt][nt][3] + bias[nt][1]) * rc1;
                float2 h0 = *(const float2*)(hrow0 + ch0);
                float2 h1 = *(const float2*)(hrow1 + ch0);
                red_add_v2(arow0 + ch0, h0.x * w00, h0.y * w01);
                red_add_v2(arow1 + ch0, h1.x * w10, h1.y * w11);
            }
        }
    }
}

extern "C" void kernel_launch(void* const* d_in, const int* in_sizes, int n_in,
                              void* d_out, int out_size)
{
    const float* x     = (const float*)d_in[0];
    const float* f_ij  = (const float*)d_in[1];
    const int*   idx_i = (const int*)d_in[2];
    const int*   idx_j = (const int*)d_in[3];
    const float* rcut  = (const float*)d_in[4];
    const float* W_in  = (const float*)d_in[5];
    const float* b_in  = (const float*)d_in[6];
    const float* W_f   = (const float*)d_in[7];
    const float* b_f   = (const float*)d_in[8];
    const float* W_out = (const float*)d_in[9];
    const float* b_out = (const float*)d_in[10];
    float* out = (float*)d_out;

    float* hptr = nullptr;
    float* aptr = nullptr;
    cudaGetSymbolAddress((void**)&hptr, g_h);
    cudaGetSymbolAddress((void**)&aptr, g_agg);

    const int n4 = N_ATOMS * DD / 4;
    zero_kernel<<<(n4 + 255) / 256, 256>>>((float4*)aptr, n4);
    gemm_atoms<false><<<N_ATOMS / 64, 256>>>(x, W_in, b_in, hptr, N_ATOMS);
    pair_mma_kernel<<<296, 256>>>(f_ij, idx_i, idx_j, rcut, W_f, b_f, hptr, aptr);
    gemm_atoms<true><<<N_ATOMS / 64, 256>>>(aptr, W_out, b_out, out, N_ATOMS);
}

// round 7
// speedup vs baseline: 1.5671x; 1.5671x over previous
#include <cuda_runtime.h>
#include <cuda_bf16.h>
#include <cstdint>

#define N_ATOMS 40000
#define N_PAIRS 640000
#define DD 128
#define RR 20

// Scratch (allocation-free rule: static device globals)
__device__ float g_h[N_ATOMS * DD];    // 20.48 MB
__device__ float g_agg[N_ATOMS * DD];  // 20.48 MB

// Packed fp32x2 FMA (validated: GEMM at 31.9 TF/s with fma-pipe only 42% active)
#define FFMA2(acc, a, b) \
    asm("fma.rn.f32x2 %0, %1, %2, %0;" : "+l"(acc) : "l"(a), "l"(b))

__device__ __forceinline__ unsigned long long pack2(float x, float y) {
    unsigned long long d;
    asm("mov.b64 %0, {%1,%2};" : "=l"(d) : "f"(x), "f"(y));
    return d;
}
__device__ __forceinline__ void unpack2(unsigned long long d, float& x, float& y) {
    asm("mov.b64 {%0,%1}, %2;" : "=f"(x), "=f"(y) : "l"(d));
}
__device__ __forceinline__ void red_add_v2(float* addr, float a, float b) {
    asm volatile("red.global.add.v2.f32 [%0], {%1, %2};"
                 :: "l"(addr), "f"(a), "f"(b) : "memory");
}

// Branch-free shifted softplus: max(x,0) + log1p(e^-|x|) - ln2 (always finite)
__device__ __forceinline__ float sspf(float x) {
    float e = __expf(-fabsf(x));
    return fmaxf(x, 0.f) + __logf(1.f + e) - 0.69314718055994531f;
}

// -----------------------------------------------------------------------------
// Tiled SGEMM (measured 41.1us). ZERO variant also zeroes this block's slice
// of zbuf (the agg accumulator), absorbing the standalone zero kernel.
// -----------------------------------------------------------------------------
template <bool SSP, bool ZERO>
__global__ __launch_bounds__(256) void gemm_atoms(
    const float* __restrict__ A, const float* __restrict__ W,
    const float* __restrict__ bias, float* __restrict__ out,
    float* __restrict__ zbuf)
{
    __shared__ float As[16][68];
    __shared__ float Bs[16][132];

    const int tid  = threadIdx.x;
    const int tcol = tid & 31;
    const int trow = tid >> 5;
    const int a0   = blockIdx.x * 64;

    if (ZERO) {
        float4* z = (float4*)(zbuf + (size_t)a0 * DD);
        const float4 z4 = make_float4(0.f, 0.f, 0.f, 0.f);
#pragma unroll
        for (int i = 0; i < 8; i++) z[tid + i * 256] = z4;
    }

    unsigned long long accp[4][4];
#pragma unroll
    for (int p = 0; p < 4; p++)
#pragma unroll
        for (int j = 0; j < 4; j++) accp[p][j] = 0ull;

    for (int kt = 0; kt < 128; kt += 16) {
        {
            int r = tid >> 2, kg = (tid & 3) << 2;
            float4 v = *(const float4*)&A[(size_t)(a0 + r) * 128 + kt + kg];
            As[kg + 0][r] = v.x; As[kg + 1][r] = v.y;
            As[kg + 2][r] = v.z; As[kg + 3][r] = v.w;
        }
#pragma unroll
        for (int q = 0; q < 2; q++) {
            int idx = tid + q * 256;
            int c = idx >> 2, kg = (idx & 3) << 2;
            float4 v = *(const float4*)&W[(size_t)c * 128 + kt + kg];
            Bs[kg + 0][c] = v.x; Bs[kg + 1][c] = v.y;
            Bs[kg + 2][c] = v.z; Bs[kg + 3][c] = v.w;
        }
        __syncthreads();
#pragma unroll
        for (int k = 0; k < 16; k++) {
            float4 b = *(const float4*)&Bs[k][tcol * 4];
            unsigned long long bb[4];
            bb[0] = pack2(b.x, b.x); bb[1] = pack2(b.y, b.y);
            bb[2] = pack2(b.z, b.z); bb[3] = pack2(b.w, b.w);
            const unsigned long long* ap =
                (const unsigned long long*)&As[k][trow * 8];
            unsigned long long a[4];
            a[0] = ap[0]; a[1] = ap[1]; a[2] = ap[2]; a[3] = ap[3];
#pragma unroll
            for (int p = 0; p < 4; p++)
#pragma unroll
                for (int j = 0; j < 4; j++) FFMA2(accp[p][j], a[p], bb[j]);
        }
        __syncthreads();
    }

    float4 bia = *(const float4*)&bias[tcol * 4];
    float bb[4] = {bia.x, bia.y, bia.z, bia.w};
#pragma unroll
    for (int p = 0; p < 4; p++) {
        float lo[4], hi[4];
#pragma unroll
        for (int j = 0; j < 4; j++) {
            unpack2(accp[p][j], lo[j], hi[j]);
            lo[j] += bb[j]; hi[j] += bb[j];
            if (SSP) { lo[j] = sspf(lo[j]); hi[j] = sspf(hi[j]); }
        }
        size_t r0 = (size_t)(a0 + trow * 8 + 2 * p) * 128 + tcol * 4;
        *(float4*)&out[r0]       = make_float4(lo[0], lo[1], lo[2], lo[3]);
        *(float4*)&out[r0 + 128] = make_float4(hi[0], hi[1], hi[2], hi[3]);
    }
}

// -----------------------------------------------------------------------------
// Pair kernel (R1 structure + f32x2 K-packing + 2 channels/thread):
//   Wij = ssp(f_ij @ W_f^T + b_f) * rcut;  agg[idx_i] += h[idx_j] * Wij
// Block = 128 threads = 2 groups of 64; group handles one pair at a time,
// thread owns channels (2*lt, 2*lt+1). W_f packed along K in 20 u64 registers.
// Per pair/thread: 5 LDS.128 (f, broadcast) + 20 FFMA2 (two 10-deep chains,
// independent across unrolled pairs) + 2 ssp + LDG.64 gather + RED.64 scatter.
// -----------------------------------------------------------------------------
#define CHUNK 32

__global__ __launch_bounds__(128) void pair_kernel(
    const float* __restrict__ f_ij, const int* __restrict__ idx_i,
    const int* __restrict__ idx_j, const float* __restrict__ rcut,
    const float* __restrict__ W_f, const float* __restrict__ b_f,
    const float* __restrict__ h, float* __restrict__ agg)
{
    __shared__ __align__(16) float sF[CHUNK * RR];  // 2.5 KB
    __shared__ float sR[CHUNK];
    __shared__ int   sI[CHUNK];
    __shared__ int   sJ[CHUNK];

    const int tid = threadIdx.x;
    const int grp = tid >> 6;        // 0,1
    const int lt  = tid & 63;
    const int c0  = lt * 2;          // channels c0, c0+1

    // Persistent packed filter weights (rows are 80B -> float2-aligned)
    unsigned long long wk0[10], wk1[10];
    {
        const float2* r0 = (const float2*)&W_f[(size_t)c0 * RR];
        const float2* r1 = (const float2*)&W_f[(size_t)(c0 + 1) * RR];
#pragma unroll
        for (int k = 0; k < 10; k++) {
            float2 a = __ldg(&r0[k]), b = __ldg(&r1[k]);
            wk0[k] = pack2(a.x, a.y);
            wk1[k] = pack2(b.x, b.y);
        }
    }
    const float bf0 = __ldg(&b_f[c0]);
    const float bf1 = __ldg(&b_f[c0 + 1]);

    const int nchunks = N_PAIRS / CHUNK;
    for (int ch = blockIdx.x; ch < nchunks; ch += gridDim.x) {
        const int base = ch * CHUNK;
        __syncthreads();   // protect smem reuse
        {
            const float4* src = (const float4*)&f_ij[(size_t)base * RR];
            for (int i = tid; i < 160; i += 128) ((float4*)sF)[i] = src[i];
            if (tid < CHUNK) {
                sR[tid] = rcut[base + tid];
                sI[tid] = idx_i[base + tid];
                sJ[tid] = idx_j[base + tid];
            }
        }
        __syncthreads();

#pragma unroll 4
        for (int q = grp; q < CHUNK; q += 2) {
            // f row: 5 x LDS.128 broadcast; register quads alias to u64 pairs
            const float4* fq = (const float4*)&sF[q * RR];   // 80B-aligned rows? 80*q: 16B-mult ✓
            float4 v0 = fq[0], v1 = fq[1], v2 = fq[2], v3 = fq[3], v4 = fq[4];
            unsigned long long f[10];
            f[0] = pack2(v0.x, v0.y); f[1] = pack2(v0.z, v0.w);
            f[2] = pack2(v1.x, v1.y); f[3] = pack2(v1.z, v1.w);
            f[4] = pack2(v2.x, v2.y); f[5] = pack2(v2.z, v2.w);
            f[6] = pack2(v3.x, v3.y); f[7] = pack2(v3.z, v3.w);
            f[8] = pack2(v4.x, v4.y); f[9] = pack2(v4.z, v4.w);

            unsigned long long acc0 = 0ull, acc1 = 0ull;
#pragma unroll
            for (int k = 0; k < 10; k++) {
                FFMA2(acc0, f[k], wk0[k]);
                FFMA2(acc1, f[k], wk1[k]);
            }
            float l0, h0, l1, h1;
            unpack2(acc0, l0, h0);
            unpack2(acc1, l1, h1);
            const float rc = sR[q];
            const float w0 = sspf(l0 + h0 + bf0) * rc;
            const float w1 = sspf(l1 + h1 + bf1) * rc;

            const float2 hv = *(const float2*)&h[(size_t)sJ[q] * DD + c0];
            red_add_v2(&agg[(size_t)sI[q] * DD + c0], hv.x * w0, hv.y * w1);
        }
    }
}

extern "C" void kernel_launch(void* const* d_in, const int* in_sizes, int n_in,
                              void* d_out, int out_size)
{
    const float* x     = (const float*)d_in[0];
    const float* f_ij  = (const float*)d_in[1];
    const int*   idx_i = (const int*)d_in[2];
    const int*   idx_j = (const int*)d_in[3];
    const float* rcut  = (const float*)d_in[4];
    const float* W_in  = (const float*)d_in[5];
    const float* b_in  = (const float*)d_in[6];
    const float* W_f   = (const float*)d_in[7];
    const float* b_f   = (const float*)d_in[8];
    const float* W_out = (const float*)d_in[9];
    const float* b_out = (const float*)d_in[10];
    float* out = (float*)d_out;

    float* hptr = nullptr;
    float* aptr = nullptr;
    cudaGetSymbolAddress((void**)&hptr, g_h);
    cudaGetSymbolAddress((void**)&aptr, g_agg);

    // GEMM #1 also zeroes agg (absorbs the standalone zero kernel)
    gemm_atoms<false, true><<<N_ATOMS / 64, 256>>>(x, W_in, b_in, hptr, aptr);
    pair_kernel<<<2048, 128>>>(f_ij, idx_i, idx_j, rcut, W_f, b_f, hptr, aptr);
    gemm_atoms<true, false><<<N_ATOMS / 64, 256>>>(aptr, W_out, b_out, out, aptr);
}

// round 8
// speedup vs baseline: 1.6228x; 1.0355x over previous
#include <cuda_runtime.h>
#include <cuda_bf16.h>
#include <cstdint>

#define N_ATOMS 40000
#define N_PAIRS 640000
#define DD 128
#define RR 20

// Scratch (allocation-free rule: static device globals)
__device__ float g_h[N_ATOMS * DD];    // 20.48 MB
__device__ float g_agg[N_ATOMS * DD];  // 20.48 MB

// Packed fp32x2 FMA (validated: GEMM at 31.9 TF/s with fma-pipe 42% active)
#define FFMA2(acc, a, b) \
    asm("fma.rn.f32x2 %0, %1, %2, %0;" : "+l"(acc) : "l"(a), "l"(b))

__device__ __forceinline__ unsigned long long pack2(float x, float y) {
    unsigned long long d;
    asm("mov.b64 %0, {%1,%2};" : "=l"(d) : "f"(x), "f"(y));
    return d;
}
__device__ __forceinline__ void unpack2(unsigned long long d, float& x, float& y) {
    asm("mov.b64 {%0,%1}, %2;" : "=f"(x), "=f"(y) : "l"(d));
}
__device__ __forceinline__ void red_add_v2(float* addr, float a, float b) {
    asm volatile("red.global.add.v2.f32 [%0], {%1, %2};"
                 :: "l"(addr), "f"(a), "f"(b) : "memory");
}
__device__ __forceinline__ uint32_t smem_u32(const void* p) {
    uint32_t a;
    asm("{ .reg .u64 t; cvta.to.shared.u64 t, %1; cvt.u32.u64 %0, t; }"
        : "=r"(a) : "l"(p));
    return a;
}
#define CP_ASYNC16(saddr, gptr) \
    asm volatile("cp.async.ca.shared.global [%0], [%1], 16;" \
                 :: "r"(saddr), "l"(gptr) : "memory")
#define CP_COMMIT() asm volatile("cp.async.commit_group;" ::: "memory")
#define CP_WAIT0()  asm volatile("cp.async.wait_group 0;" ::: "memory")

// Branch-free shifted softplus: max(x,0) + log1p(e^-|x|) - ln2
__device__ __forceinline__ float sspf(float x) {
    float e = __expf(-fabsf(x));
    return fmaxf(x, 0.f) + (__logf(1.f + e) - 0.69314718055994531f);
}

// -----------------------------------------------------------------------------
// Tiled SGEMM (measured 39.9/41.1us; at f32x2 issue floor). ZERO variant also
// zeroes this block's slice of zbuf (absorbs the standalone zero kernel).
// -----------------------------------------------------------------------------
template <bool SSP, bool ZERO>
__global__ __launch_bounds__(256) void gemm_atoms(
    const float* __restrict__ A, const float* __restrict__ W,
    const float* __restrict__ bias, float* __restrict__ out,
    float* __restrict__ zbuf)
{
    __shared__ float As[16][68];
    __shared__ float Bs[16][132];

    const int tid  = threadIdx.x;
    const int tcol = tid & 31;
    const int trow = tid >> 5;
    const int a0   = blockIdx.x * 64;

    if (ZERO) {
        float4* z = (float4*)(zbuf + (size_t)a0 * DD);
        const float4 z4 = make_float4(0.f, 0.f, 0.f, 0.f);
#pragma unroll
        for (int i = 0; i < 8; i++) z[tid + i * 256] = z4;
    }

    unsigned long long accp[4][4];
#pragma unroll
    for (int p = 0; p < 4; p++)
#pragma unroll
        for (int j = 0; j < 4; j++) accp[p][j] = 0ull;

    for (int kt = 0; kt < 128; kt += 16) {
        {
            int r = tid >> 2, kg = (tid & 3) << 2;
            float4 v = *(const float4*)&A[(size_t)(a0 + r) * 128 + kt + kg];
            As[kg + 0][r] = v.x; As[kg + 1][r] = v.y;
            As[kg + 2][r] = v.z; As[kg + 3][r] = v.w;
        }
#pragma unroll
        for (int q = 0; q < 2; q++) {
            int idx = tid + q * 256;
            int c = idx >> 2, kg = (idx & 3) << 2;
            float4 v = *(const float4*)&W[(size_t)c * 128 + kt + kg];
            Bs[kg + 0][c] = v.x; Bs[kg + 1][c] = v.y;
            Bs[kg + 2][c] = v.z; Bs[kg + 3][c] = v.w;
        }
        __syncthreads();
#pragma unroll
        for (int k = 0; k < 16; k++) {
            float4 b = *(const float4*)&Bs[k][tcol * 4];
            unsigned long long bb[4];
            bb[0] = pack2(b.x, b.x); bb[1] = pack2(b.y, b.y);
            bb[2] = pack2(b.z, b.z); bb[3] = pack2(b.w, b.w);
            const unsigned long long* ap =
                (const unsigned long long*)&As[k][trow * 8];
            unsigned long long a[4];
            a[0] = ap[0]; a[1] = ap[1]; a[2] = ap[2]; a[3] = ap[3];
#pragma unroll
            for (int p = 0; p < 4; p++)
#pragma unroll
                for (int j = 0; j < 4; j++) FFMA2(accp[p][j], a[p], bb[j]);
        }
        __syncthreads();
    }

    float4 bia = *(const float4*)&bias[tcol * 4];
    float bb[4] = {bia.x, bia.y, bia.z, bia.w};
#pragma unroll
    for (int p = 0; p < 4; p++) {
        float lo[4], hi[4];
#pragma unroll
        for (int j = 0; j < 4; j++) {
            unpack2(accp[p][j], lo[j], hi[j]);
            lo[j] += bb[j]; hi[j] += bb[j];
            if (SSP) { lo[j] = sspf(lo[j]); hi[j] = sspf(hi[j]); }
        }
        size_t r0 = (size_t)(a0 + trow * 8 + 2 * p) * 128 + tcol * 4;
        *(float4*)&out[r0]       = make_float4(lo[0], lo[1], lo[2], lo[3]);
        *(float4*)&out[r0 + 128] = make_float4(hi[0], hi[1], hi[2], hi[3]);
    }
}

// -----------------------------------------------------------------------------
// Pair kernel, double-buffered cp.async staging:
//   Wij = ssp(f_ij @ W_f^T + b_f) * rcut;  agg[idx_i] += h[idx_j] * Wij
// 256 threads = 4 groups of 64; thread owns channels (2*lt, 2*lt+1).
// CHUNK=64 pairs per buffer; group g handles q = g, g+4, ... (16 pairs).
// Gather LDG.64 issued BEFORE the FFMA2 chain to hide L2 latency.
// -----------------------------------------------------------------------------
#define CHUNK 64

__global__ __launch_bounds__(256) void pair_kernel(
    const float* __restrict__ f_ij, const int* __restrict__ idx_i,
    const int* __restrict__ idx_j, const float* __restrict__ rcut,
    const float* __restrict__ W_f, const float* __restrict__ b_f,
    const float* __restrict__ h, float* __restrict__ agg)
{
    __shared__ __align__(16) float sF[2][CHUNK * RR];  // 2 x 5KB
    __shared__ __align__(16) float sR[2][CHUNK];
    __shared__ __align__(16) int   sI[2][CHUNK];
    __shared__ __align__(16) int   sJ[2][CHUNK];

    const int tid = threadIdx.x;
    const int grp = tid >> 6;        // 0..3
    const int lt  = tid & 63;
    const int c0  = lt * 2;          // channels c0, c0+1

    // Persistent packed filter weights (rows are 80B -> float2-aligned)
    unsigned long long wk0[10], wk1[10];
    {
        const float2* r0 = (const float2*)&W_f[(size_t)c0 * RR];
        const float2* r1 = (const float2*)&W_f[(size_t)(c0 + 1) * RR];
#pragma unroll
        for (int k = 0; k < 10; k++) {
            float2 a = __ldg(&r0[k]), b = __ldg(&r1[k]);
            wk0[k] = pack2(a.x, a.y);
            wk1[k] = pack2(b.x, b.y);
        }
    }
    const float bf0 = __ldg(&b_f[c0]);
    const float bf1 = __ldg(&b_f[c0 + 1]);

    const int nchunks = N_PAIRS / CHUNK;   // 10000

    // ---- async staging of one chunk into buffer b ----
    auto stage = [&](int ch, int b) {
        const int base = ch * CHUNK;
        const char* fsrc = (const char*)&f_ij[(size_t)base * RR];
        uint32_t sf = smem_u32(&sF[b][0]);
        // f: 64*20 floats = 320 x 16B; 256 threads -> slots tid, tid+256
        CP_ASYNC16(sf + tid * 16, fsrc + tid * 16);
        if (tid < 64) {
            CP_ASYNC16(sf + (tid + 256) * 16, fsrc + (tid + 256) * 16);
        } else if (tid < 80) {        // rcut: 16 x 16B
            int t = tid - 64;
            CP_ASYNC16(smem_u32(&sR[b][0]) + t * 16,
                       (const char*)&rcut[base] + t * 16);
        } else if (tid < 96) {        // idx_i
            int t = tid - 80;
            CP_ASYNC16(smem_u32(&sI[b][0]) + t * 16,
                       (const char*)&idx_i[base] + t * 16);
        } else if (tid < 112) {       // idx_j
            int t = tid - 96;
            CP_ASYNC16(smem_u32(&sJ[b][0]) + t * 16,
                       (const char*)&idx_j[base] + t * 16);
        }
        CP_COMMIT();
    };

    int ch = blockIdx.x;
    if (ch < nchunks) stage(ch, 0);

    int it = 0;
    for (; ch < nchunks; ch += gridDim.x, ++it) {
        const int buf = it & 1;
        CP_WAIT0();
        __syncthreads();
        const int nch = ch + gridDim.x;
        if (nch < nchunks) stage(nch, buf ^ 1);

#pragma unroll 4
        for (int q = grp; q < CHUNK; q += 4) {
            // Warp-uniform metadata + EARLY gather (hide L2 latency)
            const int   jj = sJ[buf][q];
            const int   ii = sI[buf][q];
            const float rc = sR[buf][q];
            const float2 hv = *(const float2*)&h[(size_t)jj * DD + c0];

            // f row: 5 x LDS.128 broadcast; quads alias to u64 pairs
            const float4* fq = (const float4*)&sF[buf][q * RR];
            float4 v0 = fq[0], v1 = fq[1], v2 = fq[2], v3 = fq[3], v4 = fq[4];
            unsigned long long f[10];
            f[0] = pack2(v0.x, v0.y); f[1] = pack2(v0.z, v0.w);
            f[2] = pack2(v1.x, v1.y); f[3] = pack2(v1.z, v1.w);
            f[4] = pack2(v2.x, v2.y); f[5] = pack2(v2.z, v2.w);
            f[6] = pack2(v3.x, v3.y); f[7] = pack2(v3.z, v3.w);
            f[8] = pack2(v4.x, v4.y); f[9] = pack2(v4.z, v4.w);

            // Bias folded into accumulator init
            unsigned long long acc0 = pack2(bf0, 0.f);
            unsigned long long acc1 = pack2(bf1, 0.f);
#pragma unroll
            for (int k = 0; k < 10; k++) {
                FFMA2(acc0, f[k], wk0[k]);
                FFMA2(acc1, f[k], wk1[k]);
            }
            float l0, h0, l1, h1;
            unpack2(acc0, l0, h0);
            unpack2(acc1, l1, h1);
            const float w0 = sspf(l0 + h0) * rc;
            const float w1 = sspf(l1 + h1) * rc;

            red_add_v2(&agg[(size_t)ii * DD + c0], hv.x * w0, hv.y * w1);
        }
        __syncthreads();   // compute done before this buffer is restaged
    }
}

extern "C" void kernel_launch(void* const* d_in, const int* in_sizes, int n_in,
                              void* d_out, int out_size)
{
    const float* x     = (const float*)d_in[0];
    const float* f_ij  = (const float*)d_in[1];
    const int*   idx_i = (const int*)d_in[2];
    const int*   idx_j = (const int*)d_in[3];
    const float* rcut  = (const float*)d_in[4];
    const float* W_in  = (const float*)d_in[5];
    const float* b_in  = (const float*)d_in[6];
    const float* W_f   = (const float*)d_in[7];
    const float* b_f   = (const float*)d_in[8];
    const float* W_out = (const float*)d_in[9];
    const float* b_out = (const float*)d_in[10];
    float* out = (float*)d_out;

    float* hptr = nullptr;
    float* aptr = nullptr;
    cudaGetSymbolAddress((void**)&hptr, g_h);
    cudaGetSymbolAddress((void**)&aptr, g_agg);

    // GEMM #1 also zeroes agg (absorbs the standalone zero kernel)
    gemm_atoms<false, true><<<N_ATOMS / 64, 256>>>(x, W_in, b_in, hptr, aptr);
    pair_kernel<<<1024, 256>>>(f_ij, idx_i, idx_j, rcut, W_f, b_f, hptr, aptr);
    gemm_atoms<true, false><<<N_ATOMS / 64, 256>>>(aptr, W_out, b_out, out, aptr);
}

// round 9
// speedup vs baseline: 1.6715x; 1.0300x over previous
#include <cuda_runtime.h>
#include <cuda_bf16.h>
#include <cstdint>

#define N_ATOMS 40000
#define N_PAIRS 640000
#define DD 128
#define RR 20

// Scratch (allocation-free rule: static device globals)
__device__ float g_h[N_ATOMS * DD];    // 20.48 MB
__device__ float g_agg[N_ATOMS * DD];  // 20.48 MB

// Packed fp32x2 FMA (validated: GEMM at 31.9 TF/s with fma-pipe 42% active)
#define FFMA2(acc, a, b) \
    asm("fma.rn.f32x2 %0, %1, %2, %0;" : "+l"(acc) : "l"(a), "l"(b))

__device__ __forceinline__ unsigned long long pack2(float x, float y) {
    unsigned long long d;
    asm("mov.b64 %0, {%1,%2};" : "=l"(d) : "f"(x), "f"(y));
    return d;
}
__device__ __forceinline__ void unpack2(unsigned long long d, float& x, float& y) {
    asm("mov.b64 {%0,%1}, %2;" : "=f"(x), "=f"(y) : "l"(d));
}
__device__ __forceinline__ void red_add_v4(float* addr, float a, float b,
                                           float c, float d) {
    asm volatile("red.global.add.v4.f32 [%0], {%1, %2, %3, %4};"
                 :: "l"(addr), "f"(a), "f"(b), "f"(c), "f"(d) : "memory");
}
__device__ __forceinline__ uint32_t smem_u32(const void* p) {
    uint32_t a;
    asm("{ .reg .u64 t; cvta.to.shared.u64 t, %1; cvt.u32.u64 %0, t; }"
        : "=r"(a) : "l"(p));
    return a;
}
#define CP_ASYNC16(saddr, gptr) \
    asm volatile("cp.async.ca.shared.global [%0], [%1], 16;" \
                 :: "r"(saddr), "l"(gptr) : "memory")
#define CP_COMMIT() asm volatile("cp.async.commit_group;" ::: "memory")
#define CP_WAIT0()  asm volatile("cp.async.wait_group 0;" ::: "memory")

// Branch-free shifted softplus: max(x,0) + log1p(e^-|x|) - ln2
__device__ __forceinline__ float sspf(float x) {
    float e = __expf(-fabsf(x));
    return fmaxf(x, 0.f) + (__logf(1.f + e) - 0.69314718055994531f);
}

// -----------------------------------------------------------------------------
// Tiled SGEMM (measured 39.9-41.1us; at f32x2 issue floor). ZERO variant also
// zeroes this block's slice of zbuf (absorbs the standalone zero kernel).
// -----------------------------------------------------------------------------
template <bool SSP, bool ZERO>
__global__ __launch_bounds__(256) void gemm_atoms(
    const float* __restrict__ A, const float* __restrict__ W,
    const float* __restrict__ bias, float* __restrict__ out,
    float* __restrict__ zbuf)
{
    __shared__ float As[16][68];
    __shared__ float Bs[16][132];

    const int tid  = threadIdx.x;
    const int tcol = tid & 31;
    const int trow = tid >> 5;
    const int a0   = blockIdx.x * 64;

    if (ZERO) {
        float4* z = (float4*)(zbuf + (size_t)a0 * DD);
        const float4 z4 = make_float4(0.f, 0.f, 0.f, 0.f);
#pragma unroll
        for (int i = 0; i < 8; i++) z[tid + i * 256] = z4;
    }

    unsigned long long accp[4][4];
#pragma unroll
    for (int p = 0; p < 4; p++)
#pragma unroll
        for (int j = 0; j < 4; j++) accp[p][j] = 0ull;

    for (int kt = 0; kt < 128; kt += 16) {
        {
            int r = tid >> 2, kg = (tid & 3) << 2;
            float4 v = *(const float4*)&A[(size_t)(a0 + r) * 128 + kt + kg];
            As[kg + 0][r] = v.x; As[kg + 1][r] = v.y;
            As[kg + 2][r] = v.z; As[kg + 3][r] = v.w;
        }
#pragma unroll
        for (int q = 0; q < 2; q++) {
            int idx = tid + q * 256;
            int c = idx >> 2, kg = (idx & 3) << 2;
            float4 v = *(const float4*)&W[(size_t)c * 128 + kt + kg];
            Bs[kg + 0][c] = v.x; Bs[kg + 1][c] = v.y;
            Bs[kg + 2][c] = v.z; Bs[kg + 3][c] = v.w;
        }
        __syncthreads();
#pragma unroll
        for (int k = 0; k < 16; k++) {
            float4 b = *(const float4*)&Bs[k][tcol * 4];
            unsigned long long bb[4];
            bb[0] = pack2(b.x, b.x); bb[1] = pack2(b.y, b.y);
            bb[2] = pack2(b.z, b.z); bb[3] = pack2(b.w, b.w);
            const unsigned long long* ap =
                (const unsigned long long*)&As[k][trow * 8];
            unsigned long long a[4];
            a[0] = ap[0]; a[1] = ap[1]; a[2] = ap[2]; a[3] = ap[3];
#pragma unroll
            for (int p = 0; p < 4; p++)
#pragma unroll
                for (int j = 0; j < 4; j++) FFMA2(accp[p][j], a[p], bb[j]);
        }
        __syncthreads();
    }

    float4 bia = *(const float4*)&bias[tcol * 4];
    float bb[4] = {bia.x, bia.y, bia.z, bia.w};
#pragma unroll
    for (int p = 0; p < 4; p++) {
        float lo[4], hi[4];
#pragma unroll
        for (int j = 0; j < 4; j++) {
            unpack2(accp[p][j], lo[j], hi[j]);
            lo[j] += bb[j]; hi[j] += bb[j];
            if (SSP) { lo[j] = sspf(lo[j]); hi[j] = sspf(hi[j]); }
        }
        size_t r0 = (size_t)(a0 + trow * 8 + 2 * p) * 128 + tcol * 4;
        *(float4*)&out[r0]       = make_float4(lo[0], lo[1], lo[2], lo[3]);
        *(float4*)&out[r0 + 128] = make_float4(hi[0], hi[1], hi[2], hi[3]);
    }
}

// -----------------------------------------------------------------------------
// Pair kernel v3: WARP-PER-PAIR (halves the LSU stream vs 2-warps-per-pair).
// Thread owns 4 channels (c0 = lane*4); per pair, one warp issues
//   5 LDS.128 (f, broadcast) + 3 meta LDS + 1 LDG.128 gather + 1 RED.128.
// W_f held in 40 packed u64 registers; 4 independent 10-deep FFMA2 chains.
// 128 threads/block (4 warps) to keep regs/SM at 3 CTAs; no q-unroll (the
// R3 regression was reg-spill from weight-regs x q-unroll duplication).
// cp.async double-buffered staging, CHUNK=32 pairs.
// -----------------------------------------------------------------------------
#define CHUNK 32

__global__ __launch_bounds__(128) void pair_kernel(
    const float* __restrict__ f_ij, const int* __restrict__ idx_i,
    const int* __restrict__ idx_j, const float* __restrict__ rcut,
    const float* __restrict__ W_f, const float* __restrict__ b_f,
    const float* __restrict__ h, float* __restrict__ agg)
{
    __shared__ __align__(16) float sF[2][CHUNK * RR];  // 2 x 2.5KB
    __shared__ __align__(16) float sR[2][CHUNK];
    __shared__ __align__(16) int   sI[2][CHUNK];
    __shared__ __align__(16) int   sJ[2][CHUNK];

    const int tid  = threadIdx.x;
    const int lane = tid & 31;
    const int warp = tid >> 5;       // 0..3
    const int c0   = lane * 4;       // channels c0..c0+3

    // Persistent packed filter weights for 4 channels: 40 u64 regs.
    unsigned long long wk[4][10];
    float bf[4];
#pragma unroll
    for (int c = 0; c < 4; c++) {
        const float2* row = (const float2*)&W_f[(size_t)(c0 + c) * RR];
#pragma unroll
        for (int k = 0; k < 10; k++) {
            float2 v = __ldg(&row[k]);
            wk[c][k] = pack2(v.x, v.y);
        }
        bf[c] = __ldg(&b_f[c0 + c]);
    }

    const int nchunks = N_PAIRS / CHUNK;   // 20000

    // ---- async staging of one chunk into buffer b ----
    auto stage = [&](int ch, int b) {
        const int base = ch * CHUNK;
        const char* fsrc = (const char*)&f_ij[(size_t)base * RR];
        uint32_t sf = smem_u32(&sF[b][0]);
        // f: 32*20 floats = 160 x 16B slots; 128 threads -> tid, then tid<32
        CP_ASYNC16(sf + tid * 16, fsrc + tid * 16);
        if (tid < 32) {
            CP_ASYNC16(sf + (tid + 128) * 16, fsrc + (tid + 128) * 16);
        } else if (tid < 40) {        // rcut: 8 x 16B
            int t = tid - 32;
            CP_ASYNC16(smem_u32(&sR[b][0]) + t * 16,
                       (const char*)&rcut[base] + t * 16);
        } else if (tid < 48) {        // idx_i
            int t = tid - 40;
            CP_ASYNC16(smem_u32(&sI[b][0]) + t * 16,
                       (const char*)&idx_i[base] + t * 16);
        } else if (tid < 56) {        // idx_j
            int t = tid - 48;
            CP_ASYNC16(smem_u32(&sJ[b][0]) + t * 16,
                       (const char*)&idx_j[base] + t * 16);
        }
        CP_COMMIT();
    };

    int ch = blockIdx.x;
    if (ch < nchunks) stage(ch, 0);

    int it = 0;
    for (; ch < nchunks; ch += gridDim.x, ++it) {
        const int buf = it & 1;
        CP_WAIT0();
        __syncthreads();
        const int nch = ch + gridDim.x;
        if (nch < nchunks) stage(nch, buf ^ 1);

        for (int q = warp; q < CHUNK; q += 4) {
            // Warp-uniform metadata + EARLY gather (hide L2 latency)
            const int   jj = sJ[buf][q];
            const int   ii = sI[buf][q];
            const float rc = sR[buf][q];
            const float4 hv = *(const float4*)&h[(size_t)jj * DD + c0];

            // f row: 5 x LDS.128 broadcast; quads alias to u64 pairs
            const float4* fq = (const float4*)&sF[buf][q * RR];
            float4 v0 = fq[0], v1 = fq[1], v2 = fq[2], v3 = fq[3], v4 = fq[4];
            unsigned long long f[10];
            f[0] = pack2(v0.x, v0.y); f[1] = pack2(v0.z, v0.w);
            f[2] = pack2(v1.x, v1.y); f[3] = pack2(v1.z, v1.w);
            f[4] = pack2(v2.x, v2.y); f[5] = pack2(v2.z, v2.w);
            f[6] = pack2(v3.x, v3.y); f[7] = pack2(v3.z, v3.w);
            f[8] = pack2(v4.x, v4.y); f[9] = pack2(v4.z, v4.w);

            // 4 independent 10-deep FFMA2 chains, bias folded into init
            unsigned long long a0 = pack2(bf[0], 0.f);
            unsigned long long a1 = pack2(bf[1], 0.f);
            unsigned long long a2 = pack2(bf[2], 0.f);
            unsigned long long a3 = pack2(bf[3], 0.f);
#pragma unroll
            for (int k = 0; k < 10; k++) {
                FFMA2(a0, f[k], wk[0][k]);
                FFMA2(a1, f[k], wk[1][k]);
                FFMA2(a2, f[k], wk[2][k]);
                FFMA2(a3, f[k], wk[3][k]);
            }
            float l0, h0, l1, h1, l2, h2, l3, h3;
            unpack2(a0, l0, h0); unpack2(a1, l1, h1);
            unpack2(a2, l2, h2); unpack2(a3, l3, h3);
            const float w0 = sspf(l0 + h0) * rc;
            const float w1 = sspf(l1 + h1) * rc;
            const float w2 = sspf(l2 + h2) * rc;
            const float w3 = sspf(l3 + h3) * rc;

            red_add_v4(&agg[(size_t)ii * DD + c0],
                       hv.x * w0, hv.y * w1, hv.z * w2, hv.w * w3);
        }
        __syncthreads();   // compute done before this buffer is restaged
    }
}

extern "C" void kernel_launch(void* const* d_in, const int* in_sizes, int n_in,
                              void* d_out, int out_size)
{
    const float* x     = (const float*)d_in[0];
    const float* f_ij  = (const float*)d_in[1];
    const int*   idx_i = (const int*)d_in[2];
    const int*   idx_j = (const int*)d_in[3];
    const float* rcut  = (const float*)d_in[4];
    const float* W_in  = (const float*)d_in[5];
    const float* b_in  = (const float*)d_in[6];
    const float* W_f   = (const float*)d_in[7];
    const float* b_f   = (const float*)d_in[8];
    const float* W_out = (const float*)d_in[9];
    const float* b_out = (const float*)d_in[10];
    float* out = (float*)d_out;

    float* hptr = nullptr;
    float* aptr = nullptr;
    cudaGetSymbolAddress((void**)&hptr, g_h);
    cudaGetSymbolAddress((void**)&aptr, g_agg);

    // GEMM #1 also zeroes agg (absorbs the standalone zero kernel)
    gemm_atoms<false, true><<<N_ATOMS / 64, 256>>>(x, W_in, b_in, hptr, aptr);
    pair_kernel<<<2048, 128>>>(f_ij, idx_i, idx_j, rcut, W_f, b_f, hptr, aptr);
    gemm_atoms<true, false><<<N_ATOMS / 64, 256>>>(aptr, W_out, b_out, out, aptr);
}

// round 11
// speedup vs baseline: 1.7061x; 1.0207x over previous
#include <cuda_runtime.h>
#include <cuda_bf16.h>
#include <cstdint>

#define N_ATOMS 40000
#define N_PAIRS 640000
#define DD 128
#define RR 20

// Scratch (allocation-free rule: static device globals)
__device__ float g_h[N_ATOMS * DD];    // 20.48 MB
__device__ float g_agg[N_ATOMS * DD];  // 20.48 MB

// Packed fp32x2 FMA (validated: GEMM at 31.9 TF/s with fma-pipe 42% active)
#define FFMA2(acc, a, b) \
    asm("fma.rn.f32x2 %0, %1, %2, %0;" : "+l"(acc) : "l"(a), "l"(b))

__device__ __forceinline__ unsigned long long pack2(float x, float y) {
    unsigned long long d;
    asm("mov.b64 %0, {%1,%2};" : "=l"(d) : "f"(x), "f"(y));
    return d;
}
__device__ __forceinline__ void unpack2(unsigned long long d, float& x, float& y) {
    asm("mov.b64 {%0,%1}, %2;" : "=f"(x), "=f"(y) : "l"(d));
}
__device__ __forceinline__ void red_add_v4(float* addr, float a, float b,
                                           float c, float d) {
    asm volatile("red.global.add.v4.f32 [%0], {%1, %2, %3, %4};"
                 :: "l"(addr), "f"(a), "f"(b), "f"(c), "f"(d) : "memory");
}
__device__ __forceinline__ uint32_t smem_u32(const void* p) {
    uint32_t a;
    asm("{ .reg .u64 t; cvta.to.shared.u64 t, %1; cvt.u32.u64 %0, t; }"
        : "=r"(a) : "l"(p));
    return a;
}
#define CP_ASYNC16(saddr, gptr) \
    asm volatile("cp.async.ca.shared.global [%0], [%1], 16;" \
                 :: "r"(saddr), "l"(gptr) : "memory")
#define CP_COMMIT() asm volatile("cp.async.commit_group;" ::: "memory")
#define CP_WAIT0()  asm volatile("cp.async.wait_group 0;" ::: "memory")

// Branch-free shifted softplus: max(x,0) + log1p(e^-|x|) - ln2
__device__ __forceinline__ float sspf(float x) {
    float e = __expf(-fabsf(x));
    return fmaxf(x, 0.f) + (__logf(1.f + e) - 0.69314718055994531f);
}

// -----------------------------------------------------------------------------
// Tiled SGEMM with register-prefetch pipeline: tile kt+1's LDGs are issued
// before computing tile kt, hiding gmem latency under the FFMA2 block.
// ZERO variant also zeroes this block's slice of zbuf.
// -----------------------------------------------------------------------------
template <bool SSP, bool ZERO>
__global__ __launch_bounds__(256) void gemm_atoms(
    const float* __restrict__ A, const float* __restrict__ W,
    const float* __restrict__ bias, float* __restrict__ out,
    float* __restrict__ zbuf)
{
    __shared__ float As[16][68];
    __shared__ float Bs[16][132];

    const int tid  = threadIdx.x;
    const int tcol = tid & 31;
    const int trow = tid >> 5;
    const int a0   = blockIdx.x * 64;

    // Staging coordinates
    const int ar = tid >> 2, akg = (tid & 3) << 2;           // A: row, k-group
    const int wc0 = tid >> 2,        wk0g = (tid & 3) << 2;  // W quad 0
    const int wc1 = (tid + 256) >> 2, wk1g = ((tid + 256) & 3) << 2; // W quad 1

    if (ZERO) {
        float4* z = (float4*)(zbuf + (size_t)a0 * DD);
        const float4 z4 = make_float4(0.f, 0.f, 0.f, 0.f);
#pragma unroll
        for (int i = 0; i < 8; i++) z[tid + i * 256] = z4;
    }

    unsigned long long accp[4][4];
#pragma unroll
    for (int p = 0; p < 4; p++)
#pragma unroll
        for (int j = 0; j < 4; j++) accp[p][j] = 0ull;

    // Prologue: load tile 0 into registers
    float4 va  = *(const float4*)&A[(size_t)(a0 + ar) * 128 + akg];
    float4 vw0 = *(const float4*)&W[(size_t)wc0 * 128 + wk0g];
    float4 vw1 = *(const float4*)&W[(size_t)wc1 * 128 + wk1g];

#pragma unroll
    for (int kt8 = 0; kt8 < 8; kt8++) {
        // Store staged registers to smem (transposed)
        As[akg + 0][ar] = va.x; As[akg + 1][ar] = va.y;
        As[akg + 2][ar] = va.z; As[akg + 3][ar] = va.w;
        Bs[wk0g + 0][wc0] = vw0.x; Bs[wk0g + 1][wc0] = vw0.y;
        Bs[wk0g + 2][wc0] = vw0.z; Bs[wk0g + 3][wc0] = vw0.w;
        Bs[wk1g + 0][wc1] = vw1.x; Bs[wk1g + 1][wc1] = vw1.y;
        Bs[wk1g + 2][wc1] = vw1.z; Bs[wk1g + 3][wc1] = vw1.w;
        __syncthreads();

        // Prefetch next tile (latency hidden under compute below)
        if (kt8 < 7) {
            const int kt = (kt8 + 1) * 16;
            va  = *(const float4*)&A[(size_t)(a0 + ar) * 128 + kt + akg];
            vw0 = *(const float4*)&W[(size_t)wc0 * 128 + kt + wk0g];
            vw1 = *(const float4*)&W[(size_t)wc1 * 128 + kt + wk1g];
        }

#pragma unroll
        for (int k = 0; k < 16; k++) {
            float4 b = *(const float4*)&Bs[k][tcol * 4];
            unsigned long long bb[4];
            bb[0] = pack2(b.x, b.x); bb[1] = pack2(b.y, b.y);
            bb[2] = pack2(b.z, b.z); bb[3] = pack2(b.w, b.w);
            const unsigned long long* ap =
                (const unsigned long long*)&As[k][trow * 8];
            unsigned long long a[4];
            a[0] = ap[0]; a[1] = ap[1]; a[2] = ap[2]; a[3] = ap[3];
#pragma unroll
            for (int p = 0; p < 4; p++)
#pragma unroll
                for (int j = 0; j < 4; j++) FFMA2(accp[p][j], a[p], bb[j]);
        }
        __syncthreads();
    }

    float4 bia = *(const float4*)&bias[tcol * 4];
    float bb[4] = {bia.x, bia.y, bia.z, bia.w};
#pragma unroll
    for (int p = 0; p < 4; p++) {
        float lo[4], hi[4];
#pragma unroll
        for (int j = 0; j < 4; j++) {
            unpack2(accp[p][j], lo[j], hi[j]);
            lo[j] += bb[j]; hi[j] += bb[j];
            if (SSP) { lo[j] = sspf(lo[j]); hi[j] = sspf(hi[j]); }
        }
        size_t r0 = (size_t)(a0 + trow * 8 + 2 * p) * 128 + tcol * 4;
        *(float4*)&out[r0]       = make_float4(lo[0], lo[1], lo[2], lo[3]);
        *(float4*)&out[r0 + 128] = make_float4(hi[0], hi[1], hi[2], hi[3]);
    }
}

// -----------------------------------------------------------------------------
// Pair kernel: warp-per-pair, 4 ch/thread, q-level software pipeline:
// the h[idx_j] gather (L2 ~234cyc) for q+4 is issued before computing q.
// cp.async double-buffered chunk staging, CHUNK=32 pairs.
// -----------------------------------------------------------------------------
#define CHUNK 32

__global__ __launch_bounds__(128) void pair_kernel(
    const float* __restrict__ f_ij, const int* __restrict__ idx_i,
    const int* __restrict__ idx_j, const float* __restrict__ rcut,
    const float* __restrict__ W_f, const float* __restrict__ b_f,
    const float* __restrict__ h, float* __restrict__ agg)
{
    __shared__ __align__(16) float sF[2][CHUNK * RR];  // 2 x 2.5KB
    __shared__ __align__(16) float sR[2][CHUNK];
    __shared__ __align__(16) int   sI[2][CHUNK];
    __shared__ __align__(16) int   sJ[2][CHUNK];

    const int tid  = threadIdx.x;
    const int lane = tid & 31;
    const int warp = tid >> 5;       // 0..3
    const int c0   = lane * 4;       // channels c0..c0+3

    // Persistent packed filter weights for 4 channels: 40 u64 regs.
    unsigned long long wk[4][10];
    float bf[4];
#pragma unroll
    for (int c = 0; c < 4; c++) {
        const float2* row = (const float2*)&W_f[(size_t)(c0 + c) * RR];
#pragma unroll
        for (int k = 0; k < 10; k++) {
            float2 v = __ldg(&row[k]);
            wk[c][k] = pack2(v.x, v.y);
        }
        bf[c] = __ldg(&b_f[c0 + c]);
    }

    const int nchunks = N_PAIRS / CHUNK;   // 20000

    auto stage = [&](int ch, int b) {
        const int base = ch * CHUNK;
        const char* fsrc = (const char*)&f_ij[(size_t)base * RR];
        uint32_t sf = smem_u32(&sF[b][0]);
        CP_ASYNC16(sf + tid * 16, fsrc + tid * 16);
        if (tid < 32) {
            CP_ASYNC16(sf + (tid + 128) * 16, fsrc + (tid + 128) * 16);
        } else if (tid < 40) {
            int t = tid - 32;
            CP_ASYNC16(smem_u32(&sR[b][0]) + t * 16,
                       (const char*)&rcut[base] + t * 16);
        } else if (tid < 48) {
            int t = tid - 40;
            CP_ASYNC16(smem_u32(&sI[b][0]) + t * 16,
                       (const char*)&idx_i[base] + t * 16);
        } else if (tid < 56) {
            int t = tid - 48;
            CP_ASYNC16(smem_u32(&sJ[b][0]) + t * 16,
                       (const char*)&idx_j[base] + t * 16);
        }
        CP_COMMIT();
    };

    int ch = blockIdx.x;
    if (ch < nchunks) stage(ch, 0);

    int it = 0;
    for (; ch < nchunks; ch += gridDim.x, ++it) {
        const int buf = it & 1;
        CP_WAIT0();
        __syncthreads();
        const int nch = ch + gridDim.x;
        if (nch < nchunks) stage(nch, buf ^ 1);

        // ---- q pipeline: prefetch gather for q+4 before computing q ----
        int   q  = warp;
        int   ii = sI[buf][q];
        float rc = sR[buf][q];
        float4 hv = *(const float4*)&h[(size_t)sJ[buf][q] * DD + c0];

#pragma unroll
        for (int qi = 0; qi < 8; qi++) {
            int ii2; float rc2; float4 hv2;
            if (qi < 7) {                          // compile-time branch
                const int qn = q + 4;
                ii2 = sI[buf][qn];
                rc2 = sR[buf][qn];
                hv2 = *(const float4*)&h[(size_t)sJ[buf][qn] * DD + c0];
            }

            // f row: 5 x LDS.128 broadcast; quads alias to u64 pairs
            const float4* fq = (const float4*)&sF[buf][q * RR];
            float4 v0 = fq[0], v1 = fq[1], v2 = fq[2], v3 = fq[3], v4 = fq[4];
            unsigned long long f[10];
            f[0] = pack2(v0.x, v0.y); f[1] = pack2(v0.z, v0.w);
            f[2] = pack2(v1.x, v1.y); f[3] = pack2(v1.z, v1.w);
            f[4] = pack2(v2.x, v2.y); f[5] = pack2(v2.z, v2.w);
            f[6] = pack2(v3.x, v3.y); f[7] = pack2(v3.z, v3.w);
            f[8] = pack2(v4.x, v4.y); f[9] = pack2(v4.z, v4.w);

            unsigned long long a0 = pack2(bf[0], 0.f);
            unsigned long long a1 = pack2(bf[1], 0.f);
            unsigned long long a2 = pack2(bf[2], 0.f);
            unsigned long long a3 = pack2(bf[3], 0.f);
#pragma unroll
            for (int k = 0; k < 10; k++) {
                FFMA2(a0, f[k], wk[0][k]);
                FFMA2(a1, f[k], wk[1][k]);
                FFMA2(a2, f[k], wk[2][k]);
                FFMA2(a3, f[k], wk[3][k]);
            }
            float l0, h0, l1, h1, l2, h2, l3, h3;
            unpack2(a0, l0, h0); unpack2(a1, l1, h1);
            unpack2(a2, l2, h2); unpack2(a3, l3, h3);
            const float w0 = sspf(l0 + h0) * rc;
            const float w1 = sspf(l1 + h1) * rc;
            const float w2 = sspf(l2 + h2) * rc;
            const float w3 = sspf(l3 + h3) * rc;

            red_add_v4(&agg[(size_t)ii * DD + c0],
                       hv.x * w0, hv.y * w1, hv.z * w2, hv.w * w3);

            if (qi < 7) { q += 4; ii = ii2; rc = rc2; hv = hv2; }
        }
        __syncthreads();   // compute done before this buffer is restaged
    }
}

extern "C" void kernel_launch(void* const* d_in, const int* in_sizes, int n_in,
                              void* d_out, int out_size)
{
    const float* x     = (const float*)d_in[0];
    const float* f_ij  = (const float*)d_in[1];
    const int*   idx_i = (const int*)d_in[2];
    const int*   idx_j = (const int*)d_in[3];
    const float* rcut  = (const float*)d_in[4];
    const float* W_in  = (const float*)d_in[5];
    const float* b_in  = (const float*)d_in[6];
    const float* W_f   = (const float*)d_in[7];
    const float* b_f   = (const float*)d_in[8];
    const float* W_out = (const float*)d_in[9];
    const float* b_out = (const float*)d_in[10];
    float* out = (float*)d_out;

    float* hptr = nullptr;
    float* aptr = nullptr;
    cudaGetSymbolAddress((void**)&hptr, g_h);
    cudaGetSymbolAddress((void**)&aptr, g_agg);

    // GEMM #1 also zeroes agg (absorbs the standalone zero kernel)
    gemm_atoms<false, true><<<N_ATOMS / 64, 256>>>(x, W_in, b_in, hptr, aptr);
    pair_kernel<<<2048, 128>>>(f_ij, idx_i, idx_j, rcut, W_f, b_f, hptr, aptr);
    gemm_atoms<true, false><<<N_ATOMS / 64, 256>>>(aptr, W_out, b_out, out, aptr);
}